// round 15
// baseline (speedup 1.0000x reference)
#include <cuda_runtime.h>
#include <cuda_bf16.h>
#include <cstdint>

#define MAXN 100000
#define MAXE 1600000
#define DIN  128

// ---------------------------------------------------------------------------
// Scratch (allocation-free rule: __device__ globals)
// ---------------------------------------------------------------------------
__device__ float g_dinv[MAXN];
__device__ int   g_deg[MAXN];
__device__ int   g_rowptr[MAXN];
__device__ int   g_cursor[MAXN];
__device__ int   g_csrc[MAXE];
__device__ int   g_bsum[128];
__device__ int   g_is32 = 0;   // static init; only ever transitions 0->1 for
                               // the same input data => deterministic replays
__device__ float g_bufA[(size_t)MAXN * 128];
__device__ float g_bufB[(size_t)MAXN * 128];
__device__ float g_bufC[(size_t)MAXN * 128];
// Pre-split weights: W1(128x128), W2(128x128), W3(64x128) -> 320*128 elems
__device__ __nv_bfloat16 g_wh[320 * 128];
__device__ __nv_bfloat16 g_wl[320 * 128];

// ---------------------------------------------------------------------------
// Zero degree histogram + dtype probe (first 512 int64-words; for int32 data
// they fuse (src[2i],src[2i+1]) pairs and fall out of [0,n) w.h.p.)
// ---------------------------------------------------------------------------
__global__ void k_zero_probe(const long long* __restrict__ raw, int pcnt, int n) {
    int i = blockIdx.x * blockDim.x + threadIdx.x;
    if (i < n) g_deg[i] = 0;
    if (i < pcnt) {
        long long v = raw[i];
        if (v < 0 || v >= (long long)n) g_is32 = 1;
    }
}

__global__ void k_hist(const void* __restrict__ raw, int e) {
    int i = blockIdx.x * blockDim.x + threadIdx.x;
    if (i >= e) return;
    int d = g_is32 ? ((const int*)raw)[e + i]
                   : (int)((const long long*)raw)[e + i];
    atomicAdd(&g_deg[d], 1);
}

// ---------------------------------------------------------------------------
// CSR build: exclusive scan + fill
// ---------------------------------------------------------------------------
__global__ void k_scan1(int n) {
    __shared__ int sm[1024];
    int i = blockIdx.x * 1024 + threadIdx.x;
    int v = (i < n) ? g_deg[i] : 0;
    sm[threadIdx.x] = v;
    __syncthreads();
#pragma unroll
    for (int off = 1; off < 1024; off <<= 1) {
        int t = (threadIdx.x >= off) ? sm[threadIdx.x - off] : 0;
        __syncthreads();
        sm[threadIdx.x] += t;
        __syncthreads();
    }
    if (i < n) g_rowptr[i] = sm[threadIdx.x] - v;
    if (threadIdx.x == 1023) g_bsum[blockIdx.x] = sm[1023];
}

// Fused block-offset scan + apply + rsqrt norm.
__global__ void k_scan3(int n, int nb) {
    __shared__ int sb[128];
    int tid = threadIdx.x;
    if (tid < 128) sb[tid] = (tid < nb) ? g_bsum[tid] : 0;
    __syncthreads();
#pragma unroll
    for (int off = 1; off < 128; off <<= 1) {
        int v = 0;
        if (tid < 128 && tid >= off) v = sb[tid - off];
        __syncthreads();
        if (tid < 128) sb[tid] += v;
        __syncthreads();
    }
    int i = blockIdx.x * blockDim.x + tid;
    if (i < n) {
        int blk = i >> 10;
        int off = (blk == 0) ? 0 : sb[blk - 1];
        int r = g_rowptr[i] + off;
        g_rowptr[i] = r;
        g_cursor[i] = r;
        g_dinv[i] = rsqrtf((float)g_deg[i] + 1.0f);
    }
}

__global__ void k_fill(const void* __restrict__ raw, int e) {
    int i = blockIdx.x * blockDim.x + threadIdx.x;
    if (i >= e) return;
    int s, d;
    if (g_is32) {
        const int* p = (const int*)raw;
        s = p[i]; d = p[e + i];
    } else {
        const long long* p = (const long long*)raw;
        s = (int)p[i]; d = (int)p[e + i];
    }
    int pos = atomicAdd(&g_cursor[d], 1);
    g_csrc[pos] = s;
}

// ---------------------------------------------------------------------------
// Weight split: W (fp32) -> hi/lo bf16
// ---------------------------------------------------------------------------
__global__ void k_prep_w(const float* __restrict__ W1, const float* __restrict__ W2,
                         const float* __restrict__ W3) {
    int i = blockIdx.x * blockDim.x + threadIdx.x;
    if (i >= 320 * 128) return;
    float v;
    if (i < 16384)       v = W1[i];
    else if (i < 32768)  v = W2[i - 16384];
    else                 v = W3[i - 32768];
    __nv_bfloat16 h = __float2bfloat16_rn(v);
    g_wh[i] = h;
    g_wl[i] = __float2bfloat16_rn(v - __bfloat162float(h));
}

// ---------------------------------------------------------------------------
// mma.sync bf16 split GEMM: H[128 x FOUT tile] = act(X) @ W^T
// D = Ahi*Bhi + Alo*Bhi + Ahi*Blo  (fp32 accumulate, lo*lo dropped ~2^-16)
// Fragment loads via ldmatrix.x4.  row_base allows chunked launches.
// ---------------------------------------------------------------------------
__device__ __forceinline__ void mma16816(float* c, const uint32_t* a,
                                         uint32_t b0, uint32_t b1) {
    asm volatile(
        "mma.sync.aligned.m16n8k16.row.col.f32.bf16.bf16.f32 "
        "{%0,%1,%2,%3}, {%4,%5,%6,%7}, {%8,%9}, {%0,%1,%2,%3};"
        : "+f"(c[0]), "+f"(c[1]), "+f"(c[2]), "+f"(c[3])
        : "r"(a[0]), "r"(a[1]), "r"(a[2]), "r"(a[3]), "r"(b0), "r"(b1));
}

__device__ __forceinline__ void ldsm_x4(uint32_t* r, uint32_t saddr) {
    asm volatile("ldmatrix.sync.aligned.m8n8.x4.shared.b16 {%0,%1,%2,%3}, [%4];"
                 : "=r"(r[0]), "=r"(r[1]), "=r"(r[2]), "=r"(r[3]) : "r"(saddr));
}

template <int FOUT, bool RELU>
__global__ void __launch_bounds__(256, 1) k_mma(
    const float* __restrict__ X, const __nv_bfloat16* __restrict__ Wh,
    const __nv_bfloat16* __restrict__ Wl, float* __restrict__ H, int n,
    int row_base)
{
    constexpr int RS = 136;     // smem row stride in bf16 (272B; conflict-free)
    constexpr int NT = FOUT / 8;
    extern __shared__ __nv_bfloat16 sm[];
    __nv_bfloat16* Ah = sm;                       // [8][16][RS]
    __nv_bfloat16* Al = Ah + 8 * 16 * RS;
    __nv_bfloat16* Bh = Al + 8 * 16 * RS;         // [FOUT][RS]
    __nv_bfloat16* Bl = Bh + FOUT * RS;

    const int tid = threadIdx.x, wid = tid >> 5, lane = tid & 31;
    const int row0 = row_base + blockIdx.x * 128;

    // ---- stage pre-split weights into SMEM ----
    for (int idx = tid; idx < FOUT * 32; idx += 256) {
        int r = idx >> 5, c4 = idx & 31;
        *(uint2*)&Bh[r * RS + c4 * 4] = *(const uint2*)&Wh[r * 128 + c4 * 4];
        *(uint2*)&Bl[r * RS + c4 * 4] = *(const uint2*)&Wl[r * 128 + c4 * 4];
    }

    // ---- each warp converts its 16 fp32 rows -> hi/lo bf16 (ReLU fused) ----
    __nv_bfloat16* Awh = Ah + wid * 16 * RS;
    __nv_bfloat16* Awl = Al + wid * 16 * RS;
    for (int idx = lane; idx < 16 * 32; idx += 32) {
        int r = idx >> 5, c4 = idx & 31;
        int grow = row0 + wid * 16 + r;
        float4 v = make_float4(0.f, 0.f, 0.f, 0.f);
        if (grow < n) {
            v = *(const float4*)&X[(size_t)grow * 128 + c4 * 4];
            if (RELU) {
                v.x = fmaxf(v.x, 0.f); v.y = fmaxf(v.y, 0.f);
                v.z = fmaxf(v.z, 0.f); v.w = fmaxf(v.w, 0.f);
            }
        }
        __nv_bfloat162 h01 = __floats2bfloat162_rn(v.x, v.y);
        __nv_bfloat162 h23 = __floats2bfloat162_rn(v.z, v.w);
        float2 f01 = __bfloat1622float2(h01);
        float2 f23 = __bfloat1622float2(h23);
        __nv_bfloat162 l01 = __floats2bfloat162_rn(v.x - f01.x, v.y - f01.y);
        __nv_bfloat162 l23 = __floats2bfloat162_rn(v.z - f23.x, v.w - f23.y);
        *(uint2*)&Awh[r * RS + c4 * 4] =
            make_uint2(*(uint32_t*)&h01, *(uint32_t*)&h23);
        *(uint2*)&Awl[r * RS + c4 * 4] =
            make_uint2(*(uint32_t*)&l01, *(uint32_t*)&l23);
    }
    __syncthreads();

    float acc[NT][4];
#pragma unroll
    for (int t = 0; t < NT; t++)
#pragma unroll
        for (int j = 0; j < 4; j++) acc[t][j] = 0.f;

    const int qr = lane >> 2, qc = (lane & 3) * 2;

    const uint32_t a_off = (uint32_t)(((lane & 15) * RS + ((lane >> 4) << 3)) * 2);
    const uint32_t b_off = (uint32_t)(((((lane >> 4) << 3) + (lane & 7)) * RS
                                      + (((lane >> 3) & 1) << 3)) * 2);
    const uint32_t sAh = (uint32_t)__cvta_generic_to_shared(Awh) + a_off;
    const uint32_t sAl = (uint32_t)__cvta_generic_to_shared(Awl) + a_off;
    const uint32_t sBh = (uint32_t)__cvta_generic_to_shared(Bh) + b_off;
    const uint32_t sBl = (uint32_t)__cvta_generic_to_shared(Bl) + b_off;

#pragma unroll
    for (int ks = 0; ks < 8; ks++) {
        const uint32_t kadd = (uint32_t)(ks * 16 * 2);
        uint32_t ah[4], al[4];
        ldsm_x4(ah, sAh + kadd);
        ldsm_x4(al, sAl + kadd);
#pragma unroll
        for (int ntp = 0; ntp < NT / 2; ntp++) {
            const uint32_t badd = kadd + (uint32_t)(ntp * 16 * RS * 2);
            uint32_t bh[4], bl[4];
            ldsm_x4(bh, sBh + badd);
            ldsm_x4(bl, sBl + badd);
            mma16816(acc[ntp * 2],     ah, bh[0], bh[1]);
            mma16816(acc[ntp * 2],     al, bh[0], bh[1]);
            mma16816(acc[ntp * 2],     ah, bl[0], bl[1]);
            mma16816(acc[ntp * 2 + 1], ah, bh[2], bh[3]);
            mma16816(acc[ntp * 2 + 1], al, bh[2], bh[3]);
            mma16816(acc[ntp * 2 + 1], ah, bl[2], bl[3]);
        }
    }

    // ---- epilogue ----
    const int r0 = row0 + wid * 16 + qr;
    const int r1 = r0 + 8;
#pragma unroll
    for (int nt = 0; nt < NT; nt++) {
        int col = nt * 8 + qc;
        if (r0 < n)
            *(float2*)&H[(size_t)r0 * FOUT + col] = make_float2(acc[nt][0], acc[nt][1]);
        if (r1 < n)
            *(float2*)&H[(size_t)r1 * FOUT + col] = make_float2(acc[nt][2], acc[nt][3]);
    }
}

// ---------------------------------------------------------------------------
// CSR aggregation over node range [node0, node1): warp per dst node.
// OUT[d] = bias + dinv[d] * ( dinv[d]*H[d] + sum_{s in in(d)} dinv[s]*H[s] )
// ---------------------------------------------------------------------------
__global__ void __launch_bounds__(256) k_agg128(
    const float* __restrict__ H, const float* __restrict__ bias,
    float* __restrict__ OUT, int node0, int node1)
{
    int node = node0 + blockIdx.x * 8 + (threadIdx.x >> 5);
    if (node >= node1) return;
    int lane = threadIdx.x & 31;

    int beg = g_rowptr[node];
    int end = beg + g_deg[node];

    float4 acc = make_float4(0.f, 0.f, 0.f, 0.f);
    int j = beg;
    for (; j + 4 <= end; j += 4) {
        int s0 = g_csrc[j], s1 = g_csrc[j + 1];
        int s2 = g_csrc[j + 2], s3 = g_csrc[j + 3];
        float w0 = g_dinv[s0], w1 = g_dinv[s1];
        float w2 = g_dinv[s2], w3 = g_dinv[s3];
        float4 v0 = *(const float4*)&H[(size_t)s0 * 128 + lane * 4];
        float4 v1 = *(const float4*)&H[(size_t)s1 * 128 + lane * 4];
        float4 v2 = *(const float4*)&H[(size_t)s2 * 128 + lane * 4];
        float4 v3 = *(const float4*)&H[(size_t)s3 * 128 + lane * 4];
        acc.x += w0 * v0.x + w1 * v1.x + w2 * v2.x + w3 * v3.x;
        acc.y += w0 * v0.y + w1 * v1.y + w2 * v2.y + w3 * v3.y;
        acc.z += w0 * v0.z + w1 * v1.z + w2 * v2.z + w3 * v3.z;
        acc.w += w0 * v0.w + w1 * v1.w + w2 * v2.w + w3 * v3.w;
    }
    for (; j < end; j++) {
        int s = g_csrc[j];
        float w = g_dinv[s];
        float4 v = *(const float4*)&H[(size_t)s * 128 + lane * 4];
        acc.x += w * v.x; acc.y += w * v.y;
        acc.z += w * v.z; acc.w += w * v.w;
    }

    float di = g_dinv[node];
    float4 hs = *(const float4*)&H[(size_t)node * 128 + lane * 4];
    float4 bb = *(const float4*)&bias[lane * 4];
    float4 o;
    o.x = bb.x + di * (acc.x + di * hs.x);
    o.y = bb.y + di * (acc.y + di * hs.y);
    o.z = bb.z + di * (acc.z + di * hs.z);
    o.w = bb.w + di * (acc.w + di * hs.w);
    *(float4*)&OUT[(size_t)node * 128 + lane * 4] = o;
}

__global__ void __launch_bounds__(256) k_agg64(
    const float* __restrict__ H, const float* __restrict__ bias,
    float* __restrict__ OUT, int n)
{
    int node = blockIdx.x * 8 + (threadIdx.x >> 5);
    if (node >= n) return;
    int lane = threadIdx.x & 31;

    int beg = g_rowptr[node];
    int end = beg + g_deg[node];

    float2 acc = make_float2(0.f, 0.f);
    int j = beg;
    for (; j + 4 <= end; j += 4) {
        int s0 = g_csrc[j], s1 = g_csrc[j + 1];
        int s2 = g_csrc[j + 2], s3 = g_csrc[j + 3];
        float w0 = g_dinv[s0], w1 = g_dinv[s1];
        float w2 = g_dinv[s2], w3 = g_dinv[s3];
        float2 v0 = *(const float2*)&H[(size_t)s0 * 64 + lane * 2];
        float2 v1 = *(const float2*)&H[(size_t)s1 * 64 + lane * 2];
        float2 v2 = *(const float2*)&H[(size_t)s2 * 64 + lane * 2];
        float2 v3 = *(const float2*)&H[(size_t)s3 * 64 + lane * 2];
        acc.x += w0 * v0.x + w1 * v1.x + w2 * v2.x + w3 * v3.x;
        acc.y += w0 * v0.y + w1 * v1.y + w2 * v2.y + w3 * v3.y;
    }
    for (; j < end; j++) {
        int s = g_csrc[j];
        float w = g_dinv[s];
        float2 v = *(const float2*)&H[(size_t)s * 64 + lane * 2];
        acc.x += w * v.x; acc.y += w * v.y;
    }

    float di = g_dinv[node];
    float2 hs = *(const float2*)&H[(size_t)node * 64 + lane * 2];
    float2 bb = *(const float2*)&bias[lane * 2];
    float2 o;
    o.x = bb.x + di * (acc.x + di * hs.x);
    o.y = bb.y + di * (acc.y + di * hs.y);
    *(float2*)&OUT[(size_t)node * 64 + lane * 2] = o;         // mu
    *(float2*)&OUT[(size_t)(n + node) * 64 + lane * 2] = o;   // logstd
}

// ---------------------------------------------------------------------------
extern "C" void kernel_launch(void* const* d_in, const int* in_sizes, int n_in,
                              void* d_out, int out_size)
{
    const float* x  = (const float*)d_in[0];
    const float* W1 = (const float*)d_in[1];
    const float* b1 = (const float*)d_in[2];
    const float* W2 = (const float*)d_in[3];
    const float* b2 = (const float*)d_in[4];
    const float* W3 = (const float*)d_in[5];
    const float* b3 = (const float*)d_in[6];
    const void*  ei = d_in[7];

    int n = in_sizes[0] / DIN;
    int e = in_sizes[7] / 2;
    float* out = (float*)d_out;

    // Lazy one-time stream/event creation (host-side resources only).
    static cudaStream_t s_aux = nullptr;
    static cudaEvent_t  ev[8];
    if (!s_aux) {
        cudaStreamCreateWithFlags(&s_aux, cudaStreamNonBlocking);
        for (int i = 0; i < 8; i++)
            cudaEventCreateWithFlags(&ev[i], cudaEventDisableTiming);
    }

    float *bufA, *bufB, *bufC;
    cudaGetSymbolAddress((void**)&bufA, g_bufA);
    cudaGetSymbolAddress((void**)&bufB, g_bufB);
    cudaGetSymbolAddress((void**)&bufC, g_bufC);
    __nv_bfloat16 *wh, *wl;
    cudaGetSymbolAddress((void**)&wh, g_wh);
    cudaGetSymbolAddress((void**)&wl, g_wl);

    constexpr int RS = 136;
    const int SMEM128 = (8 * 16 * RS * 2 + 128 * RS * 2) * 2;  // ~136 KB
    const int SMEM64  = (8 * 16 * RS * 2 + 64 * RS * 2) * 2;   // ~102 KB
    cudaFuncSetAttribute(k_mma<128, false>,
                         cudaFuncAttributeMaxDynamicSharedMemorySize, SMEM128);
    cudaFuncSetAttribute(k_mma<128, true>,
                         cudaFuncAttributeMaxDynamicSharedMemorySize, SMEM128);
    cudaFuncSetAttribute(k_mma<64, true>,
                         cudaFuncAttributeMaxDynamicSharedMemorySize, SMEM64);

    int nb  = (n + 255) / 256;
    int ebk = (e + 255) / 256;
    int nsb = (n + 1023) / 1024;

    int gb = (n + 127) / 128;       // GEMM tiles total
    int t0 = gb / 2;                // chunk0 tiles
    int h  = t0 * 128;              // chunk0 node count (h <= n)
    int agc0 = (h + 7) / 8;
    int agc1 = (n - h + 7) / 8;
    int ag   = (n + 7) / 8;

    // --- fork: CSR build on aux stream; weight-split + GEMM1 on main ---
    cudaEventRecord(ev[0], 0);
    cudaStreamWaitEvent(s_aux, ev[0], 0);

    k_zero_probe<<<nb, 256, 0, s_aux>>>((const long long*)ei,
                                        512 < e ? 512 : e, n);
    k_hist<<<ebk, 256, 0, s_aux>>>(ei, e);
    k_scan1<<<nsb, 1024, 0, s_aux>>>(n);
    k_scan3<<<nb, 256, 0, s_aux>>>(n, nsb);
    k_fill<<<ebk, 256, 0, s_aux>>>(ei, e);
    cudaEventRecord(ev[1], s_aux);

    k_prep_w<<<160, 256>>>(W1, W2, W3);
    // GEMM1: x -> H1 (bufA)   [independent of CSR]
    k_mma<128, false><<<gb, 256, SMEM128>>>(x, wh, wl, bufA, n, 0);

    cudaStreamWaitEvent(0, ev[1], 0);   // CSR ready

    // --- L1 agg (bufA -> bufB) chunked; GEMM2 (bufB -> bufC) overlapped ---
    k_agg128<<<agc0, 256>>>(bufA, b1, bufB, 0, h);
    cudaEventRecord(ev[2], 0);
    k_agg128<<<agc1, 256>>>(bufA, b1, bufB, h, n);
    cudaEventRecord(ev[3], 0);
    cudaStreamWaitEvent(s_aux, ev[2], 0);
    k_mma<128, true><<<t0, 256, SMEM128, s_aux>>>(bufB, wh + 16384, wl + 16384,
                                                  bufC, n, 0);
    cudaStreamWaitEvent(s_aux, ev[3], 0);
    k_mma<128, true><<<gb - t0, 256, SMEM128, s_aux>>>(bufB, wh + 16384,
                                                       wl + 16384, bufC, n, h);
    cudaEventRecord(ev[4], s_aux);
    cudaStreamWaitEvent(0, ev[4], 0);   // H2 complete

    // --- L2 agg (bufC -> bufA) chunked; GEMM3 (bufA -> bufB) overlapped ---
    k_agg128<<<agc0, 256>>>(bufC, b2, bufA, 0, h);
    cudaEventRecord(ev[5], 0);
    k_agg128<<<agc1, 256>>>(bufC, b2, bufA, h, n);
    cudaEventRecord(ev[6], 0);
    cudaStreamWaitEvent(s_aux, ev[5], 0);
    k_mma<64, true><<<t0, 256, SMEM64, s_aux>>>(bufA, wh + 32768, wl + 32768,
                                                bufB, n, 0);
    cudaStreamWaitEvent(s_aux, ev[6], 0);
    k_mma<64, true><<<gb - t0, 256, SMEM64, s_aux>>>(bufA, wh + 32768,
                                                     wl + 32768, bufB, n, h);
    cudaEventRecord(ev[7], s_aux);
    cudaStreamWaitEvent(0, ev[7], 0);   // H3 complete

    // --- final aggregation (bufB -> out): mu & logstd ---
    k_agg64<<<ag, 256>>>(bufB, b3, out, n);
}

// round 16
// speedup vs baseline: 1.1752x; 1.1752x over previous
#include <cuda_runtime.h>
#include <cuda_bf16.h>
#include <cstdint>

#define MAXN 100000
#define MAXE 1600000
#define DIN  128

// ---------------------------------------------------------------------------
// Scratch (allocation-free rule: __device__ globals)
// ---------------------------------------------------------------------------
__device__ float g_dinv[MAXN];
__device__ int   g_deg[MAXN];
__device__ int   g_rowptr[MAXN];
__device__ int   g_cursor[MAXN];
__device__ int   g_csrc[MAXE];
__device__ int   g_bsum[128];
__device__ int   g_is32 = 0;   // static init; only ever transitions 0->1 for
                               // the same input data => deterministic replays
__device__ float g_bufA[(size_t)MAXN * 128];
__device__ float g_bufB[(size_t)MAXN * 128];
// Pre-split weights: W1(128x128), W2(128x128), W3(64x128) -> 320*128 elems
__device__ __nv_bfloat16 g_wh[320 * 128];
__device__ __nv_bfloat16 g_wl[320 * 128];

// ---------------------------------------------------------------------------
// Zero degree histogram + dtype probe (first 512 int64-words; for int32 data
// they fuse (src[2i],src[2i+1]) pairs and fall out of [0,n) w.h.p.)
// ---------------------------------------------------------------------------
__global__ void k_zero_probe(const long long* __restrict__ raw, int pcnt, int n) {
    int i = blockIdx.x * blockDim.x + threadIdx.x;
    if (i < n) g_deg[i] = 0;
    if (i < pcnt) {
        long long v = raw[i];
        if (v < 0 || v >= (long long)n) g_is32 = 1;
    }
}

__global__ void k_hist(const void* __restrict__ raw, int e) {
    int i = blockIdx.x * blockDim.x + threadIdx.x;
    if (i >= e) return;
    int d = g_is32 ? ((const int*)raw)[e + i]
                   : (int)((const long long*)raw)[e + i];
    atomicAdd(&g_deg[d], 1);
}

// ---------------------------------------------------------------------------
// CSR build: exclusive scan + fill
// ---------------------------------------------------------------------------
__global__ void k_scan1(int n) {
    __shared__ int sm[1024];
    int i = blockIdx.x * 1024 + threadIdx.x;
    int v = (i < n) ? g_deg[i] : 0;
    sm[threadIdx.x] = v;
    __syncthreads();
#pragma unroll
    for (int off = 1; off < 1024; off <<= 1) {
        int t = (threadIdx.x >= off) ? sm[threadIdx.x - off] : 0;
        __syncthreads();
        sm[threadIdx.x] += t;
        __syncthreads();
    }
    if (i < n) g_rowptr[i] = sm[threadIdx.x] - v;
    if (threadIdx.x == 1023) g_bsum[blockIdx.x] = sm[1023];
}

// Fused block-offset scan + apply + rsqrt norm.
__global__ void k_scan3(int n, int nb) {
    __shared__ int sb[128];
    int tid = threadIdx.x;
    if (tid < 128) sb[tid] = (tid < nb) ? g_bsum[tid] : 0;
    __syncthreads();
#pragma unroll
    for (int off = 1; off < 128; off <<= 1) {
        int v = 0;
        if (tid < 128 && tid >= off) v = sb[tid - off];
        __syncthreads();
        if (tid < 128) sb[tid] += v;
        __syncthreads();
    }
    int i = blockIdx.x * blockDim.x + tid;
    if (i < n) {
        int blk = i >> 10;
        int off = (blk == 0) ? 0 : sb[blk - 1];
        int r = g_rowptr[i] + off;
        g_rowptr[i] = r;
        g_cursor[i] = r;
        g_dinv[i] = rsqrtf((float)g_deg[i] + 1.0f);
    }
}

__global__ void k_fill(const void* __restrict__ raw, int e) {
    int i = blockIdx.x * blockDim.x + threadIdx.x;
    if (i >= e) return;
    int s, d;
    if (g_is32) {
        const int* p = (const int*)raw;
        s = p[i]; d = p[e + i];
    } else {
        const long long* p = (const long long*)raw;
        s = (int)p[i]; d = (int)p[e + i];
    }
    int pos = atomicAdd(&g_cursor[d], 1);
    g_csrc[pos] = s;
}

// ---------------------------------------------------------------------------
// Weight split: W (fp32) -> hi/lo bf16
// ---------------------------------------------------------------------------
__global__ void k_prep_w(const float* __restrict__ W1, const float* __restrict__ W2,
                         const float* __restrict__ W3) {
    int i = blockIdx.x * blockDim.x + threadIdx.x;
    if (i >= 320 * 128) return;
    float v;
    if (i < 16384)       v = W1[i];
    else if (i < 32768)  v = W2[i - 16384];
    else                 v = W3[i - 32768];
    __nv_bfloat16 h = __float2bfloat16_rn(v);
    g_wh[i] = h;
    g_wl[i] = __float2bfloat16_rn(v - __bfloat162float(h));
}

// ---------------------------------------------------------------------------
// mma.sync bf16 split GEMM: H[64-row x FOUT tile] = act(X) @ W^T
// D = Ahi*Bhi + Alo*Bhi + Ahi*Blo  (fp32 accumulate, lo*lo dropped ~2^-16)
// 64-row M-tile -> ~102 KB smem -> 2 blocks/SM (load/MMA phases of co-resident
// blocks overlap; halves tail waves).  8 warps = 4 row-groups x 2 col-halves.
// ---------------------------------------------------------------------------
__device__ __forceinline__ void mma16816(float* c, const uint32_t* a,
                                         uint32_t b0, uint32_t b1) {
    asm volatile(
        "mma.sync.aligned.m16n8k16.row.col.f32.bf16.bf16.f32 "
        "{%0,%1,%2,%3}, {%4,%5,%6,%7}, {%8,%9}, {%0,%1,%2,%3};"
        : "+f"(c[0]), "+f"(c[1]), "+f"(c[2]), "+f"(c[3])
        : "r"(a[0]), "r"(a[1]), "r"(a[2]), "r"(a[3]), "r"(b0), "r"(b1));
}

__device__ __forceinline__ void ldsm_x4(uint32_t* r, uint32_t saddr) {
    asm volatile("ldmatrix.sync.aligned.m8n8.x4.shared.b16 {%0,%1,%2,%3}, [%4];"
                 : "=r"(r[0]), "=r"(r[1]), "=r"(r[2]), "=r"(r[3]) : "r"(saddr));
}

template <int FOUT, bool RELU>
__global__ void __launch_bounds__(256, 2) k_mma(
    const float* __restrict__ X, const __nv_bfloat16* __restrict__ Wh,
    const __nv_bfloat16* __restrict__ Wl, float* __restrict__ H, int n)
{
    constexpr int RS = 136;       // smem row stride in bf16 (272B; conflict-free)
    constexpr int NHALF = FOUT / 2;    // cols per warp col-half
    constexpr int NT = NHALF / 8;      // n-tiles per warp (8 for 128, 4 for 64)
    extern __shared__ __nv_bfloat16 sm[];
    __nv_bfloat16* Ah = sm;                       // [64][RS]
    __nv_bfloat16* Al = Ah + 64 * RS;
    __nv_bfloat16* Bh = Al + 64 * RS;             // [FOUT][RS]
    __nv_bfloat16* Bl = Bh + FOUT * RS;

    const int tid = threadIdx.x, wid = tid >> 5, lane = tid & 31;
    const int row0 = blockIdx.x * 64;
    const int wrow = (wid & 3) * 16;   // warp row-group base within tile
    const int wcol = (wid >> 2) * NHALF;  // warp col-half base

    // ---- stage pre-split weights into SMEM ----
    for (int idx = tid; idx < FOUT * 32; idx += 256) {
        int r = idx >> 5, c4 = idx & 31;
        *(uint2*)&Bh[r * RS + c4 * 4] = *(const uint2*)&Wh[r * 128 + c4 * 4];
        *(uint2*)&Bl[r * RS + c4 * 4] = *(const uint2*)&Wl[r * 128 + c4 * 4];
    }

    // ---- convert 64 fp32 rows -> hi/lo bf16 (ReLU fused), block-strided ----
    for (int idx = tid; idx < 64 * 32; idx += 256) {
        int r = idx >> 5, c4 = idx & 31;
        int grow = row0 + r;
        float4 v = make_float4(0.f, 0.f, 0.f, 0.f);
        if (grow < n) {
            v = *(const float4*)&X[(size_t)grow * 128 + c4 * 4];
            if (RELU) {
                v.x = fmaxf(v.x, 0.f); v.y = fmaxf(v.y, 0.f);
                v.z = fmaxf(v.z, 0.f); v.w = fmaxf(v.w, 0.f);
            }
        }
        __nv_bfloat162 h01 = __floats2bfloat162_rn(v.x, v.y);
        __nv_bfloat162 h23 = __floats2bfloat162_rn(v.z, v.w);
        float2 f01 = __bfloat1622float2(h01);
        float2 f23 = __bfloat1622float2(h23);
        __nv_bfloat162 l01 = __floats2bfloat162_rn(v.x - f01.x, v.y - f01.y);
        __nv_bfloat162 l23 = __floats2bfloat162_rn(v.z - f23.x, v.w - f23.y);
        *(uint2*)&Ah[r * RS + c4 * 4] =
            make_uint2(*(uint32_t*)&h01, *(uint32_t*)&h23);
        *(uint2*)&Al[r * RS + c4 * 4] =
            make_uint2(*(uint32_t*)&l01, *(uint32_t*)&l23);
    }
    __syncthreads();

    float acc[NT][4];
#pragma unroll
    for (int t = 0; t < NT; t++)
#pragma unroll
        for (int j = 0; j < 4; j++) acc[t][j] = 0.f;

    const int qr = lane >> 2, qc = (lane & 3) * 2;

    // ldmatrix lane addressing (relative to warp's A row-group / B col-half):
    // A x4: (m0-7,k0-7)(m8-15,k0-7)(m0-7,k8-15)(m8-15,k8-15) -> a0..a3
    // B x4 covers TWO n-tiles: regs b0,b1 = tile nt, b2,b3 = tile nt+1
    const uint32_t a_off = (uint32_t)(((wrow + (lane & 15)) * RS
                                      + ((lane >> 4) << 3)) * 2);
    const uint32_t b_off = (uint32_t)(((wcol + ((lane >> 4) << 3) + (lane & 7)) * RS
                                      + (((lane >> 3) & 1) << 3)) * 2);
    const uint32_t sAh = (uint32_t)__cvta_generic_to_shared(Ah) + a_off;
    const uint32_t sAl = (uint32_t)__cvta_generic_to_shared(Al) + a_off;
    const uint32_t sBh = (uint32_t)__cvta_generic_to_shared(Bh) + b_off;
    const uint32_t sBl = (uint32_t)__cvta_generic_to_shared(Bl) + b_off;

#pragma unroll
    for (int ks = 0; ks < 8; ks++) {
        const uint32_t kadd = (uint32_t)(ks * 16 * 2);
        uint32_t ah[4], al[4];
        ldsm_x4(ah, sAh + kadd);
        ldsm_x4(al, sAl + kadd);
#pragma unroll
        for (int ntp = 0; ntp < NT / 2; ntp++) {
            const uint32_t badd = kadd + (uint32_t)(ntp * 16 * RS * 2);
            uint32_t bh[4], bl[4];
            ldsm_x4(bh, sBh + badd);
            ldsm_x4(bl, sBl + badd);
            mma16816(acc[ntp * 2],     ah, bh[0], bh[1]);
            mma16816(acc[ntp * 2],     al, bh[0], bh[1]);
            mma16816(acc[ntp * 2],     ah, bl[0], bl[1]);
            mma16816(acc[ntp * 2 + 1], ah, bh[2], bh[3]);
            mma16816(acc[ntp * 2 + 1], al, bh[2], bh[3]);
            mma16816(acc[ntp * 2 + 1], ah, bl[2], bl[3]);
        }
    }

    // ---- epilogue ----
    const int r0 = row0 + wrow + qr;
    const int r1 = r0 + 8;
#pragma unroll
    for (int nt = 0; nt < NT; nt++) {
        int col = wcol + nt * 8 + qc;
        if (r0 < n)
            *(float2*)&H[(size_t)r0 * FOUT + col] = make_float2(acc[nt][0], acc[nt][1]);
        if (r1 < n)
            *(float2*)&H[(size_t)r1 * FOUT + col] = make_float2(acc[nt][2], acc[nt][3]);
    }
}

// ---------------------------------------------------------------------------
// CSR aggregation: one warp per dst node, register accumulation, no atomics.
// OUT[d] = bias + dinv[d] * ( dinv[d]*H[d] + sum_{s in in(d)} dinv[s]*H[s] )
// High occupancy (no smem) is load-bearing: gather phase is L2-latency-bound.
// ---------------------------------------------------------------------------
__global__ void __launch_bounds__(256) k_agg128(
    const float* __restrict__ H, const float* __restrict__ bias,
    float* __restrict__ OUT, int n)
{
    int node = blockIdx.x * 8 + (threadIdx.x >> 5);
    if (node >= n) return;
    int lane = threadIdx.x & 31;

    int beg = g_rowptr[node];
    int end = beg + g_deg[node];

    float4 acc = make_float4(0.f, 0.f, 0.f, 0.f);
    int j = beg;
    for (; j + 4 <= end; j += 4) {
        int s0 = g_csrc[j], s1 = g_csrc[j + 1];
        int s2 = g_csrc[j + 2], s3 = g_csrc[j + 3];
        float w0 = g_dinv[s0], w1 = g_dinv[s1];
        float w2 = g_dinv[s2], w3 = g_dinv[s3];
        float4 v0 = *(const float4*)&H[(size_t)s0 * 128 + lane * 4];
        float4 v1 = *(const float4*)&H[(size_t)s1 * 128 + lane * 4];
        float4 v2 = *(const float4*)&H[(size_t)s2 * 128 + lane * 4];
        float4 v3 = *(const float4*)&H[(size_t)s3 * 128 + lane * 4];
        acc.x += w0 * v0.x + w1 * v1.x + w2 * v2.x + w3 * v3.x;
        acc.y += w0 * v0.y + w1 * v1.y + w2 * v2.y + w3 * v3.y;
        acc.z += w0 * v0.z + w1 * v1.z + w2 * v2.z + w3 * v3.z;
        acc.w += w0 * v0.w + w1 * v1.w + w2 * v2.w + w3 * v3.w;
    }
    for (; j < end; j++) {
        int s = g_csrc[j];
        float w = g_dinv[s];
        float4 v = *(const float4*)&H[(size_t)s * 128 + lane * 4];
        acc.x += w * v.x; acc.y += w * v.y;
        acc.z += w * v.z; acc.w += w * v.w;
    }

    float di = g_dinv[node];
    float4 hs = *(const float4*)&H[(size_t)node * 128 + lane * 4];
    float4 bb = *(const float4*)&bias[lane * 4];
    float4 o;
    o.x = bb.x + di * (acc.x + di * hs.x);
    o.y = bb.y + di * (acc.y + di * hs.y);
    o.z = bb.z + di * (acc.z + di * hs.z);
    o.w = bb.w + di * (acc.w + di * hs.w);
    *(float4*)&OUT[(size_t)node * 128 + lane * 4] = o;
}

__global__ void __launch_bounds__(256) k_agg64(
    const float* __restrict__ H, const float* __restrict__ bias,
    float* __restrict__ OUT, int n)
{
    int node = blockIdx.x * 8 + (threadIdx.x >> 5);
    if (node >= n) return;
    int lane = threadIdx.x & 31;

    int beg = g_rowptr[node];
    int end = beg + g_deg[node];

    float2 acc = make_float2(0.f, 0.f);
    int j = beg;
    for (; j + 4 <= end; j += 4) {
        int s0 = g_csrc[j], s1 = g_csrc[j + 1];
        int s2 = g_csrc[j + 2], s3 = g_csrc[j + 3];
        float w0 = g_dinv[s0], w1 = g_dinv[s1];
        float w2 = g_dinv[s2], w3 = g_dinv[s3];
        float2 v0 = *(const float2*)&H[(size_t)s0 * 64 + lane * 2];
        float2 v1 = *(const float2*)&H[(size_t)s1 * 64 + lane * 2];
        float2 v2 = *(const float2*)&H[(size_t)s2 * 64 + lane * 2];
        float2 v3 = *(const float2*)&H[(size_t)s3 * 64 + lane * 2];
        acc.x += w0 * v0.x + w1 * v1.x + w2 * v2.x + w3 * v3.x;
        acc.y += w0 * v0.y + w1 * v1.y + w2 * v2.y + w3 * v3.y;
    }
    for (; j < end; j++) {
        int s = g_csrc[j];
        float w = g_dinv[s];
        float2 v = *(const float2*)&H[(size_t)s * 64 + lane * 2];
        acc.x += w * v.x; acc.y += w * v.y;
    }

    float di = g_dinv[node];
    float2 hs = *(const float2*)&H[(size_t)node * 64 + lane * 2];
    float2 bb = *(const float2*)&bias[lane * 2];
    float2 o;
    o.x = bb.x + di * (acc.x + di * hs.x);
    o.y = bb.y + di * (acc.y + di * hs.y);
    *(float2*)&OUT[(size_t)node * 64 + lane * 2] = o;         // mu
    *(float2*)&OUT[(size_t)(n + node) * 64 + lane * 2] = o;   // logstd
}

// ---------------------------------------------------------------------------
extern "C" void kernel_launch(void* const* d_in, const int* in_sizes, int n_in,
                              void* d_out, int out_size)
{
    const float* x  = (const float*)d_in[0];
    const float* W1 = (const float*)d_in[1];
    const float* b1 = (const float*)d_in[2];
    const float* W2 = (const float*)d_in[3];
    const float* b2 = (const float*)d_in[4];
    const float* W3 = (const float*)d_in[5];
    const float* b3 = (const float*)d_in[6];
    const void*  ei = d_in[7];

    int n = in_sizes[0] / DIN;
    int e = in_sizes[7] / 2;
    float* out = (float*)d_out;

    // Lazy one-time stream/event creation (host-side resources only).
    static cudaStream_t s_aux = nullptr;
    static cudaEvent_t  s_fork = nullptr, s_join = nullptr;
    if (!s_aux) {
        cudaStreamCreateWithFlags(&s_aux, cudaStreamNonBlocking);
        cudaEventCreateWithFlags(&s_fork, cudaEventDisableTiming);
        cudaEventCreateWithFlags(&s_join, cudaEventDisableTiming);
    }

    float *bufA, *bufB;
    cudaGetSymbolAddress((void**)&bufA, g_bufA);
    cudaGetSymbolAddress((void**)&bufB, g_bufB);
    __nv_bfloat16 *wh, *wl;
    cudaGetSymbolAddress((void**)&wh, g_wh);
    cudaGetSymbolAddress((void**)&wl, g_wl);

    constexpr int RS = 136;
    const int SMEM128 = (64 * RS * 2 + 128 * RS * 2) * 2;  // ~102 KB -> 2/SM
    const int SMEM64  = (64 * RS * 2 + 64 * RS * 2) * 2;   // ~68 KB  -> 3/SM
    cudaFuncSetAttribute(k_mma<128, false>,
                         cudaFuncAttributeMaxDynamicSharedMemorySize, SMEM128);
    cudaFuncSetAttribute(k_mma<128, true>,
                         cudaFuncAttributeMaxDynamicSharedMemorySize, SMEM128);
    cudaFuncSetAttribute(k_mma<64, true>,
                         cudaFuncAttributeMaxDynamicSharedMemorySize, SMEM64);

    int nb  = (n + 255) / 256;
    int ebk = (e + 255) / 256;
    int nsb = (n + 1023) / 1024;

    int gb = (n + 63) / 64;     // GEMM tiles (64 rows each)
    int ag = (n + 7) / 8;       // agg blocks

    // --- fork: CSR build on aux stream, weight-split + GEMM1 on main ---
    cudaEventRecord(s_fork, 0);
    cudaStreamWaitEvent(s_aux, s_fork, 0);

    k_zero_probe<<<nb, 256, 0, s_aux>>>((const long long*)ei,
                                        512 < e ? 512 : e, n);
    k_hist<<<ebk, 256, 0, s_aux>>>(ei, e);
    k_scan1<<<nsb, 1024, 0, s_aux>>>(n);
    k_scan3<<<nb, 256, 0, s_aux>>>(n, nsb);
    k_fill<<<ebk, 256, 0, s_aux>>>(ei, e);
    cudaEventRecord(s_join, s_aux);

    k_prep_w<<<160, 256>>>(W1, W2, W3);
    // Layer 1 GEMM (independent of CSR)
    k_mma<128, false><<<gb, 256, SMEM128>>>(x, wh, wl, bufA, n);

    // --- join: aggregations need the CSR ---
    cudaStreamWaitEvent(0, s_join, 0);

    k_agg128<<<ag, 256>>>(bufA, b1, bufB, n);
    // Layer 2
    k_mma<128, true><<<gb, 256, SMEM128>>>(bufB, wh + 16384, wl + 16384, bufA, n);
    k_agg128<<<ag, 256>>>(bufA, b2, bufB, n);
    // Layer 3 (FOUT=64) -> mu & logstd
    k_mma<64, true><<<gb, 256, SMEM64>>>(bufB, wh + 32768, wl + 32768, bufA, n);
    k_agg64<<<ag, 256>>>(bufA, b3, out, n);
}

// round 17
// speedup vs baseline: 1.3259x; 1.1282x over previous
#include <cuda_runtime.h>
#include <cuda_bf16.h>
#include <cuda_fp16.h>
#include <cstdint>

#define MAXN 100000
#define MAXE 1600000
#define DIN  128

// ---------------------------------------------------------------------------
// Scratch (allocation-free rule: __device__ globals)
// ---------------------------------------------------------------------------
__device__ float g_dinv[MAXN];
__device__ int   g_deg[MAXN];
__device__ int   g_rowptr[MAXN];
__device__ int   g_cursor[MAXN];
__device__ int   g_csrc[MAXE];
__device__ int   g_bsum[128];
__device__ int   g_is32 = 0;   // static init; only ever transitions 0->1 for
                               // the same input data => deterministic replays
__device__ float  g_bufA[(size_t)MAXN * 128];   // fp32 agg outputs (OUT1/OUT2)
__device__ float  g_bufB[(size_t)MAXN * 128];
__device__ __half g_bufH[(size_t)MAXN * 128];   // fp16 GEMM outputs (H1/H2/H3)
// Pre-split weights: W1(128x128), W2(128x128), W3(64x128) -> 320*128 elems
__device__ __nv_bfloat16 g_wh[320 * 128];
__device__ __nv_bfloat16 g_wl[320 * 128];

// ---------------------------------------------------------------------------
// Zero degree histogram + dtype probe (first 512 int64-words; for int32 data
// they fuse (src[2i],src[2i+1]) pairs and fall out of [0,n) w.h.p.)
// ---------------------------------------------------------------------------
__global__ void k_zero_probe(const long long* __restrict__ raw, int pcnt, int n) {
    int i = blockIdx.x * blockDim.x + threadIdx.x;
    if (i < n) g_deg[i] = 0;
    if (i < pcnt) {
        long long v = raw[i];
        if (v < 0 || v >= (long long)n) g_is32 = 1;
    }
}

__global__ void k_hist(const void* __restrict__ raw, int e) {
    int i = blockIdx.x * blockDim.x + threadIdx.x;
    if (i >= e) return;
    int d = g_is32 ? ((const int*)raw)[e + i]
                   : (int)((const long long*)raw)[e + i];
    atomicAdd(&g_deg[d], 1);
}

// ---------------------------------------------------------------------------
// CSR build: exclusive scan + fill
// ---------------------------------------------------------------------------
__global__ void k_scan1(int n) {
    __shared__ int sm[1024];
    int i = blockIdx.x * 1024 + threadIdx.x;
    int v = (i < n) ? g_deg[i] : 0;
    sm[threadIdx.x] = v;
    __syncthreads();
#pragma unroll
    for (int off = 1; off < 1024; off <<= 1) {
        int t = (threadIdx.x >= off) ? sm[threadIdx.x - off] : 0;
        __syncthreads();
        sm[threadIdx.x] += t;
        __syncthreads();
    }
    if (i < n) g_rowptr[i] = sm[threadIdx.x] - v;
    if (threadIdx.x == 1023) g_bsum[blockIdx.x] = sm[1023];
}

// Fused block-offset scan + apply + rsqrt norm.
__global__ void k_scan3(int n, int nb) {
    __shared__ int sb[128];
    int tid = threadIdx.x;
    if (tid < 128) sb[tid] = (tid < nb) ? g_bsum[tid] : 0;
    __syncthreads();
#pragma unroll
    for (int off = 1; off < 128; off <<= 1) {
        int v = 0;
        if (tid < 128 && tid >= off) v = sb[tid - off];
        __syncthreads();
        if (tid < 128) sb[tid] += v;
        __syncthreads();
    }
    int i = blockIdx.x * blockDim.x + tid;
    if (i < n) {
        int blk = i >> 10;
        int off = (blk == 0) ? 0 : sb[blk - 1];
        int r = g_rowptr[i] + off;
        g_rowptr[i] = r;
        g_cursor[i] = r;
        g_dinv[i] = rsqrtf((float)g_deg[i] + 1.0f);
    }
}

__global__ void k_fill(const void* __restrict__ raw, int e) {
    int i = blockIdx.x * blockDim.x + threadIdx.x;
    if (i >= e) return;
    int s, d;
    if (g_is32) {
        const int* p = (const int*)raw;
        s = p[i]; d = p[e + i];
    } else {
        const long long* p = (const long long*)raw;
        s = (int)p[i]; d = (int)p[e + i];
    }
    int pos = atomicAdd(&g_cursor[d], 1);
    g_csrc[pos] = s;
}

// ---------------------------------------------------------------------------
// Weight split: W (fp32) -> hi/lo bf16
// ---------------------------------------------------------------------------
__global__ void k_prep_w(const float* __restrict__ W1, const float* __restrict__ W2,
                         const float* __restrict__ W3) {
    int i = blockIdx.x * blockDim.x + threadIdx.x;
    if (i >= 320 * 128) return;
    float v;
    if (i < 16384)       v = W1[i];
    else if (i < 32768)  v = W2[i - 16384];
    else                 v = W3[i - 32768];
    __nv_bfloat16 h = __float2bfloat16_rn(v);
    g_wh[i] = h;
    g_wl[i] = __float2bfloat16_rn(v - __bfloat162float(h));
}

// ---------------------------------------------------------------------------
// mma.sync bf16 split GEMM: H[64-row x FOUT tile] = act(X) @ W^T
// D = Ahi*Bhi + Alo*Bhi + Ahi*Blo  (fp32 accumulate, lo*lo dropped ~2^-16)
// 64-row M-tile -> 2-3 blocks/SM.  Output stored fp16 (optionally pre-scaled
// by dinv[row] so downstream aggregation is a pure row-sum).
// ---------------------------------------------------------------------------
__device__ __forceinline__ void mma16816(float* c, const uint32_t* a,
                                         uint32_t b0, uint32_t b1) {
    asm volatile(
        "mma.sync.aligned.m16n8k16.row.col.f32.bf16.bf16.f32 "
        "{%0,%1,%2,%3}, {%4,%5,%6,%7}, {%8,%9}, {%0,%1,%2,%3};"
        : "+f"(c[0]), "+f"(c[1]), "+f"(c[2]), "+f"(c[3])
        : "r"(a[0]), "r"(a[1]), "r"(a[2]), "r"(a[3]), "r"(b0), "r"(b1));
}

__device__ __forceinline__ void ldsm_x4(uint32_t* r, uint32_t saddr) {
    asm volatile("ldmatrix.sync.aligned.m8n8.x4.shared.b16 {%0,%1,%2,%3}, [%4];"
                 : "=r"(r[0]), "=r"(r[1]), "=r"(r[2]), "=r"(r[3]) : "r"(saddr));
}

template <int FOUT, bool RELU, bool PRESCALE>
__global__ void __launch_bounds__(256, 2) k_mma(
    const float* __restrict__ X, const __nv_bfloat16* __restrict__ Wh,
    const __nv_bfloat16* __restrict__ Wl, __half* __restrict__ H, int n)
{
    constexpr int RS = 136;       // smem row stride in bf16 (272B; conflict-free)
    constexpr int NHALF = FOUT / 2;
    constexpr int NT = NHALF / 8;
    extern __shared__ __nv_bfloat16 sm[];
    __nv_bfloat16* Ah = sm;                       // [64][RS]
    __nv_bfloat16* Al = Ah + 64 * RS;
    __nv_bfloat16* Bh = Al + 64 * RS;             // [FOUT][RS]
    __nv_bfloat16* Bl = Bh + FOUT * RS;

    const int tid = threadIdx.x, wid = tid >> 5, lane = tid & 31;
    const int row0 = blockIdx.x * 64;
    const int wrow = (wid & 3) * 16;
    const int wcol = (wid >> 2) * NHALF;

    // ---- stage pre-split weights into SMEM ----
    for (int idx = tid; idx < FOUT * 32; idx += 256) {
        int r = idx >> 5, c4 = idx & 31;
        *(uint2*)&Bh[r * RS + c4 * 4] = *(const uint2*)&Wh[r * 128 + c4 * 4];
        *(uint2*)&Bl[r * RS + c4 * 4] = *(const uint2*)&Wl[r * 128 + c4 * 4];
    }

    // ---- convert 64 fp32 rows -> hi/lo bf16 (ReLU fused), block-strided ----
    for (int idx = tid; idx < 64 * 32; idx += 256) {
        int r = idx >> 5, c4 = idx & 31;
        int grow = row0 + r;
        float4 v = make_float4(0.f, 0.f, 0.f, 0.f);
        if (grow < n) {
            v = *(const float4*)&X[(size_t)grow * 128 + c4 * 4];
            if (RELU) {
                v.x = fmaxf(v.x, 0.f); v.y = fmaxf(v.y, 0.f);
                v.z = fmaxf(v.z, 0.f); v.w = fmaxf(v.w, 0.f);
            }
        }
        __nv_bfloat162 h01 = __floats2bfloat162_rn(v.x, v.y);
        __nv_bfloat162 h23 = __floats2bfloat162_rn(v.z, v.w);
        float2 f01 = __bfloat1622float2(h01);
        float2 f23 = __bfloat1622float2(h23);
        __nv_bfloat162 l01 = __floats2bfloat162_rn(v.x - f01.x, v.y - f01.y);
        __nv_bfloat162 l23 = __floats2bfloat162_rn(v.z - f23.x, v.w - f23.y);
        *(uint2*)&Ah[r * RS + c4 * 4] =
            make_uint2(*(uint32_t*)&h01, *(uint32_t*)&h23);
        *(uint2*)&Al[r * RS + c4 * 4] =
            make_uint2(*(uint32_t*)&l01, *(uint32_t*)&l23);
    }
    __syncthreads();

    float acc[NT][4];
#pragma unroll
    for (int t = 0; t < NT; t++)
#pragma unroll
        for (int j = 0; j < 4; j++) acc[t][j] = 0.f;

    const int qr = lane >> 2, qc = (lane & 3) * 2;

    const uint32_t a_off = (uint32_t)(((wrow + (lane & 15)) * RS
                                      + ((lane >> 4) << 3)) * 2);
    const uint32_t b_off = (uint32_t)(((wcol + ((lane >> 4) << 3) + (lane & 7)) * RS
                                      + (((lane >> 3) & 1) << 3)) * 2);
    const uint32_t sAh = (uint32_t)__cvta_generic_to_shared(Ah) + a_off;
    const uint32_t sAl = (uint32_t)__cvta_generic_to_shared(Al) + a_off;
    const uint32_t sBh = (uint32_t)__cvta_generic_to_shared(Bh) + b_off;
    const uint32_t sBl = (uint32_t)__cvta_generic_to_shared(Bl) + b_off;

#pragma unroll
    for (int ks = 0; ks < 8; ks++) {
        const uint32_t kadd = (uint32_t)(ks * 16 * 2);
        uint32_t ah[4], al[4];
        ldsm_x4(ah, sAh + kadd);
        ldsm_x4(al, sAl + kadd);
#pragma unroll
        for (int ntp = 0; ntp < NT / 2; ntp++) {
            const uint32_t badd = kadd + (uint32_t)(ntp * 16 * RS * 2);
            uint32_t bh[4], bl[4];
            ldsm_x4(bh, sBh + badd);
            ldsm_x4(bl, sBl + badd);
            mma16816(acc[ntp * 2],     ah, bh[0], bh[1]);
            mma16816(acc[ntp * 2],     al, bh[0], bh[1]);
            mma16816(acc[ntp * 2],     ah, bl[0], bl[1]);
            mma16816(acc[ntp * 2 + 1], ah, bh[2], bh[3]);
            mma16816(acc[ntp * 2 + 1], al, bh[2], bh[3]);
            mma16816(acc[ntp * 2 + 1], ah, bl[2], bl[3]);
        }
    }

    // ---- epilogue: fp16 store (optionally pre-scaled by dinv[row]) ----
    const int r0 = row0 + wrow + qr;
    const int r1 = r0 + 8;
    float s0 = 1.f, s1 = 1.f;
    if (PRESCALE) {
        if (r0 < n) s0 = g_dinv[r0];
        if (r1 < n) s1 = g_dinv[r1];
    }
#pragma unroll
    for (int nt = 0; nt < NT; nt++) {
        int col = wcol + nt * 8 + qc;
        if (r0 < n)
            *(__half2*)&H[(size_t)r0 * FOUT + col] =
                __floats2half2_rn(acc[nt][0] * s0, acc[nt][1] * s0);
        if (r1 < n)
            *(__half2*)&H[(size_t)r1 * FOUT + col] =
                __floats2half2_rn(acc[nt][2] * s1, acc[nt][3] * s1);
    }
}

// ---------------------------------------------------------------------------
// CSR aggregation over fp16 H: one warp per dst node, no atomics.
// SCALED:  H already holds dinv[s]*h  -> OUT = b + dinv[d]*(sum + H[d])
// !SCALED: OUT = b + dinv[d]*(sum dinv[s]*H[s] + dinv[d]*H[d])
// ---------------------------------------------------------------------------
__device__ __forceinline__ float4 h4f(uint2 u) {
    __half2 a = *(__half2*)&u.x, b = *(__half2*)&u.y;
    float2 fa = __half22float2(a), fb = __half22float2(b);
    return make_float4(fa.x, fa.y, fb.x, fb.y);
}

template <bool SCALED>
__global__ void __launch_bounds__(256) k_aggh128(
    const __half* __restrict__ H, const float* __restrict__ bias,
    float* __restrict__ OUT, int n)
{
    int node = blockIdx.x * 8 + (threadIdx.x >> 5);
    if (node >= n) return;
    int lane = threadIdx.x & 31;

    int beg = g_rowptr[node];
    int end = beg + g_deg[node];

    float4 acc = make_float4(0.f, 0.f, 0.f, 0.f);
    int j = beg;
    for (; j + 4 <= end; j += 4) {
        int s0 = g_csrc[j], s1 = g_csrc[j + 1];
        int s2 = g_csrc[j + 2], s3 = g_csrc[j + 3];
        float4 v0 = h4f(*(const uint2*)&H[(size_t)s0 * 128 + lane * 4]);
        float4 v1 = h4f(*(const uint2*)&H[(size_t)s1 * 128 + lane * 4]);
        float4 v2 = h4f(*(const uint2*)&H[(size_t)s2 * 128 + lane * 4]);
        float4 v3 = h4f(*(const uint2*)&H[(size_t)s3 * 128 + lane * 4]);
        if (SCALED) {
            acc.x += v0.x + v1.x + v2.x + v3.x;
            acc.y += v0.y + v1.y + v2.y + v3.y;
            acc.z += v0.z + v1.z + v2.z + v3.z;
            acc.w += v0.w + v1.w + v2.w + v3.w;
        } else {
            float w0 = g_dinv[s0], w1 = g_dinv[s1];
            float w2 = g_dinv[s2], w3 = g_dinv[s3];
            acc.x += w0 * v0.x + w1 * v1.x + w2 * v2.x + w3 * v3.x;
            acc.y += w0 * v0.y + w1 * v1.y + w2 * v2.y + w3 * v3.y;
            acc.z += w0 * v0.z + w1 * v1.z + w2 * v2.z + w3 * v3.z;
            acc.w += w0 * v0.w + w1 * v1.w + w2 * v2.w + w3 * v3.w;
        }
    }
    for (; j < end; j++) {
        int s = g_csrc[j];
        float4 v = h4f(*(const uint2*)&H[(size_t)s * 128 + lane * 4]);
        if (SCALED) {
            acc.x += v.x; acc.y += v.y; acc.z += v.z; acc.w += v.w;
        } else {
            float w = g_dinv[s];
            acc.x += w * v.x; acc.y += w * v.y;
            acc.z += w * v.z; acc.w += w * v.w;
        }
    }

    float di = g_dinv[node];
    float4 hs = h4f(*(const uint2*)&H[(size_t)node * 128 + lane * 4]);
    float sf = SCALED ? 1.f : di;     // self term: SCALED already has dinv
    float4 bb = *(const float4*)&bias[lane * 4];
    float4 o;
    o.x = bb.x + di * (acc.x + sf * hs.x);
    o.y = bb.y + di * (acc.y + sf * hs.y);
    o.z = bb.z + di * (acc.z + sf * hs.z);
    o.w = bb.w + di * (acc.w + sf * hs.w);
    *(float4*)&OUT[(size_t)node * 128 + lane * 4] = o;
}

// Width-64, SCALED input; writes mu and logstd (duplicate).
__global__ void __launch_bounds__(256) k_aggh64(
    const __half* __restrict__ H, const float* __restrict__ bias,
    float* __restrict__ OUT, int n)
{
    int node = blockIdx.x * 8 + (threadIdx.x >> 5);
    if (node >= n) return;
    int lane = threadIdx.x & 31;

    int beg = g_rowptr[node];
    int end = beg + g_deg[node];

    float2 acc = make_float2(0.f, 0.f);
    int j = beg;
    for (; j + 4 <= end; j += 4) {
        int s0 = g_csrc[j], s1 = g_csrc[j + 1];
        int s2 = g_csrc[j + 2], s3 = g_csrc[j + 3];
        float2 v0 = __half22float2(*(const __half2*)&H[(size_t)s0 * 64 + lane * 2]);
        float2 v1 = __half22float2(*(const __half2*)&H[(size_t)s1 * 64 + lane * 2]);
        float2 v2 = __half22float2(*(const __half2*)&H[(size_t)s2 * 64 + lane * 2]);
        float2 v3 = __half22float2(*(const __half2*)&H[(size_t)s3 * 64 + lane * 2]);
        acc.x += v0.x + v1.x + v2.x + v3.x;
        acc.y += v0.y + v1.y + v2.y + v3.y;
    }
    for (; j < end; j++) {
        int s = g_csrc[j];
        float2 v = __half22float2(*(const __half2*)&H[(size_t)s * 64 + lane * 2]);
        acc.x += v.x; acc.y += v.y;
    }

    float di = g_dinv[node];
    float2 hs = __half22float2(*(const __half2*)&H[(size_t)node * 64 + lane * 2]);
    float2 bb = *(const float2*)&bias[lane * 2];
    float2 o;
    o.x = bb.x + di * (acc.x + hs.x);
    o.y = bb.y + di * (acc.y + hs.y);
    *(float2*)&OUT[(size_t)node * 64 + lane * 2] = o;         // mu
    *(float2*)&OUT[(size_t)(n + node) * 64 + lane * 2] = o;   // logstd
}

// ---------------------------------------------------------------------------
extern "C" void kernel_launch(void* const* d_in, const int* in_sizes, int n_in,
                              void* d_out, int out_size)
{
    const float* x  = (const float*)d_in[0];
    const float* W1 = (const float*)d_in[1];
    const float* b1 = (const float*)d_in[2];
    const float* W2 = (const float*)d_in[3];
    const float* b2 = (const float*)d_in[4];
    const float* W3 = (const float*)d_in[5];
    const float* b3 = (const float*)d_in[6];
    const void*  ei = d_in[7];

    int n = in_sizes[0] / DIN;
    int e = in_sizes[7] / 2;
    float* out = (float*)d_out;

    // Lazy one-time stream/event creation (host-side resources only).
    static cudaStream_t s_aux = nullptr;
    static cudaEvent_t  s_fork = nullptr, s_join = nullptr;
    if (!s_aux) {
        cudaStreamCreateWithFlags(&s_aux, cudaStreamNonBlocking);
        cudaEventCreateWithFlags(&s_fork, cudaEventDisableTiming);
        cudaEventCreateWithFlags(&s_join, cudaEventDisableTiming);
    }

    float *bufA, *bufB;
    __half* bufH;
    cudaGetSymbolAddress((void**)&bufA, g_bufA);
    cudaGetSymbolAddress((void**)&bufB, g_bufB);
    cudaGetSymbolAddress((void**)&bufH, g_bufH);
    __nv_bfloat16 *wh, *wl;
    cudaGetSymbolAddress((void**)&wh, g_wh);
    cudaGetSymbolAddress((void**)&wl, g_wl);

    constexpr int RS = 136;
    const int SMEM128 = (64 * RS * 2 + 128 * RS * 2) * 2;  // ~102 KB -> 2/SM
    const int SMEM64  = (64 * RS * 2 + 64 * RS * 2) * 2;   // ~68 KB  -> 3/SM
    cudaFuncSetAttribute(k_mma<128, false, false>,
                         cudaFuncAttributeMaxDynamicSharedMemorySize, SMEM128);
    cudaFuncSetAttribute(k_mma<128, true, true>,
                         cudaFuncAttributeMaxDynamicSharedMemorySize, SMEM128);
    cudaFuncSetAttribute(k_mma<64, true, true>,
                         cudaFuncAttributeMaxDynamicSharedMemorySize, SMEM64);

    int nb  = (n + 255) / 256;
    int ebk = (e + 255) / 256;
    int nsb = (n + 1023) / 1024;

    int gb = (n + 63) / 64;     // GEMM tiles (64 rows each)
    int ag = (n + 7) / 8;       // agg blocks

    // --- fork: CSR build on aux stream, weight-split + GEMM1 on main ---
    cudaEventRecord(s_fork, 0);
    cudaStreamWaitEvent(s_aux, s_fork, 0);

    k_zero_probe<<<nb, 256, 0, s_aux>>>((const long long*)ei,
                                        512 < e ? 512 : e, n);
    k_hist<<<ebk, 256, 0, s_aux>>>(ei, e);
    k_scan1<<<nsb, 1024, 0, s_aux>>>(n);
    k_scan3<<<nb, 256, 0, s_aux>>>(n, nsb);
    k_fill<<<ebk, 256, 0, s_aux>>>(ei, e);
    cudaEventRecord(s_join, s_aux);

    k_prep_w<<<160, 256>>>(W1, W2, W3);
    // Layer 1 GEMM (independent of CSR; no prescale -- dinv not ready yet)
    k_mma<128, false, false><<<gb, 256, SMEM128>>>(x, wh, wl, bufH, n);

    // --- join: aggregations need the CSR ---
    cudaStreamWaitEvent(0, s_join, 0);

    // L1 agg: H1 (fp16, unscaled) -> OUT1 (fp32)
    k_aggh128<false><<<ag, 256>>>(bufH, b1, bufA, n);
    // Layer 2 GEMM: relu(OUT1) @ W2^T -> H2 (fp16, pre-scaled by dinv)
    k_mma<128, true, true><<<gb, 256, SMEM128>>>(bufA, wh + 16384, wl + 16384,
                                                 bufH, n);
    // L2 agg: pure row-sum
    k_aggh128<true><<<ag, 256>>>(bufH, b2, bufB, n);
    // Layer 3 GEMM (FOUT=64): relu(OUT2) @ W3^T -> H3 (fp16, pre-scaled)
    k_mma<64, true, true><<<gb, 256, SMEM64>>>(bufB, wh + 32768, wl + 32768,
                                               bufH, n);
    // Final agg -> mu & logstd
    k_aggh64<<<ag, 256>>>(bufH, b3, out, n);
}